// round 7
// baseline (speedup 1.0000x reference)
#include <cuda_runtime.h>
#include <cstdint>

#define TT   28
#define IND  28
#define HID  64
#define EE   8
#define ES   8         // operand row stride = EE floats (32B)
#define OUTD 10
#define NT   512
#define K0P  96        // layer0 padded K (28 x + 64 h + 4 zero)
#define KSL0 12        // layer0 K-slice
#define KSL1 16        // layer1 K-slice

// Shared memory (floats):
//  h1seq [TT][HID][ES]          = 14336
//  zbuf  [96][ES]               =   768  (x rows 0..27, h0 rows 28..91, zero 92..95)
//  hs    [HID][ES]              =   512
//  xch   ulonglong2[8*8*64]     = 16384
//  actx  float4[4*64]           =  1024
//  wlin  640, blin 16
#define OFF_H1SEQ 0
#define OFF_ZBUF  (OFF_H1SEQ + TT*HID*ES)
#define OFF_HS    (OFF_ZBUF + K0P*ES)
#define OFF_XCH   (OFF_HS + HID*ES)
#define OFF_ACTX  (OFF_XCH + 8*8*64*4)
#define OFF_WLIN  (OFF_ACTX + 4*64*4)
#define OFF_BLIN  (OFF_WLIN + OUTD*HID)
#define SMEM_FLOATS (OFF_BLIN + 16)
#define SMEM_BYTES  (SMEM_FLOATS * 4)

typedef unsigned long long u64;

__device__ __forceinline__ u64 splat2(float w) {
    u64 r; asm("mov.b64 %0, {%1, %1};" : "=l"(r) : "f"(w)); return r;
}
__device__ __forceinline__ void ffma2(u64& d, u64 a, u64 b) {
    asm("fma.rn.f32x2 %0, %1, %2, %0;" : "+l"(d) : "l"(a), "l"(b));
}
__device__ __forceinline__ void fadd2(u64& d, u64 a) {
    asm("add.rn.f32x2 %0, %1, %0;" : "+l"(d) : "l"(a));
}
__device__ __forceinline__ float2 unpack2(u64 v) {
    float2 f; asm("mov.b64 {%0, %1}, %2;" : "=f"(f.x), "=f"(f.y) : "l"(v)); return f;
}
__device__ __forceinline__ float tanhfast(float x) {
    float r; asm("tanh.approx.f32 %0, %1;" : "=f"(r) : "f"(x)); return r;
}
__device__ __forceinline__ float sigfast(float x) {
    return fmaf(0.5f, tanhfast(0.5f * x), 0.5f);
}

// Gate partial: 4 gate rows of one unit, 8 batch elems, NK k-steps.
// Per k: 2 LDS.128 (broadcast) + 4 splat + 16 FFMA2.
template<int NK>
__device__ __forceinline__ void gate_partial(const float* __restrict__ base,
                                             const float* w0, const float* w1,
                                             const float* w2, const float* w3,
                                             u64 a0[4], u64 a1[4], u64 a2[4], u64 a3[4])
{
#pragma unroll
    for (int k = 0; k < NK; k++) {
        const ulonglong2* p = reinterpret_cast<const ulonglong2*>(base + k * ES);
        ulonglong2 qa = p[0], qb = p[1];     // e0..3, e4..7 as f32x2 pairs
        u64 s0 = splat2(w0[k]);
        u64 s1 = splat2(w1[k]);
        u64 s2 = splat2(w2[k]);
        u64 s3 = splat2(w3[k]);
        ffma2(a0[0], qa.x, s0); ffma2(a0[1], qa.y, s0); ffma2(a0[2], qb.x, s0); ffma2(a0[3], qb.y, s0);
        ffma2(a1[0], qa.x, s1); ffma2(a1[1], qa.y, s1); ffma2(a1[2], qb.x, s1); ffma2(a1[3], qb.y, s1);
        ffma2(a2[0], qa.x, s2); ffma2(a2[1], qa.y, s2); ffma2(a2[2], qb.x, s2); ffma2(a2[3], qb.y, s2);
        ffma2(a3[0], qa.x, s3); ffma2(a3[1], qa.y, s3); ffma2(a3[2], qb.x, s3); ffma2(a3[3], qb.y, s3);
    }
}

// Ship all 8 (rowgroup,pair) buckets; combine own bucket (8 sources) + bias;
// activate; exchange g,o -> (i,f) owner; update cell; write h.
// Returns via pointers. rg0 threads (ks<4) own cells (u, e=2p,2p+1).
__device__ __forceinline__ void exchange_update(
    ulonglong2* xch, float4* actx,
    u64 a0[4], u64 a1[4], u64 a2[4], u64 a3[4],
    int u, int ks, u64 biasP0, u64 biasP1,
    float& c0, float& c1,
    float* __restrict__ hdst0, float* __restrict__ hdst1,   // up to two h destinations (row base for unit u)
    int p_ownL)   // column pair this thread owns (ks&3); valid for ks<4 update
{
    // ship: bucket b holds (rows rg*2, rg*2+1) partials for pair b&3
#pragma unroll
    for (int b = 0; b < 8; b++) {
        int pr = b & 3;
        u64 lo = (b < 4) ? a0[pr] : a2[pr];
        u64 hi = (b < 4) ? a1[pr] : a3[pr];
        xch[(b * 8 + ks) * 64 + u] = make_ulonglong2(lo, hi);
    }
    __syncthreads();

    // combine own bucket (= ks)
    u64 s0 = biasP0, s1 = biasP1;
#pragma unroll
    for (int src = 0; src < 8; src++) {
        ulonglong2 v = xch[(ks * 8 + src) * 64 + u];
        fadd2(s0, v.x);
        fadd2(s1, v.y);
    }

    if (ks >= 4) {
        // rows u+128 (g), u+192 (o)
        float2 g2 = unpack2(s0), o2 = unpack2(s1);
        float g0 = tanhfast(g2.x), g1 = tanhfast(g2.y);
        float o0 = sigfast(o2.x),  o1 = sigfast(o2.y);
        actx[(ks - 4) * 64 + u] = make_float4(g0, g1, o0, o1);
    }
    __syncthreads();

    if (ks < 4) {
        // rows u (i), u+64 (f); read g,o from peer
        float2 i2 = unpack2(s0), f2 = unpack2(s1);
        float4 go = actx[p_ownL * 64 + u];
        float i0 = sigfast(i2.x), i1 = sigfast(i2.y);
        float f0 = sigfast(f2.x), f1 = sigfast(f2.y);
        c0 = f0 * c0 + i0 * go.x;
        c1 = f1 * c1 + i1 * go.y;
        float h0 = go.z * tanhfast(c0);
        float h1 = go.w * tanhfast(c1);
        float2 hv = make_float2(h0, h1);
        *reinterpret_cast<float2*>(hdst0 + 2 * p_ownL) = hv;
        if (hdst1) *reinterpret_cast<float2*>(hdst1 + 2 * p_ownL) = hv;
    }
}

__global__ void __launch_bounds__(NT, 1)
rnn_fused_kernel(const float* __restrict__ x,
                 const float* __restrict__ Wih0, const float* __restrict__ Whh0,
                 const float* __restrict__ bih0, const float* __restrict__ bhh0,
                 const float* __restrict__ Wih1, const float* __restrict__ Whh1,
                 const float* __restrict__ bih1, const float* __restrict__ bhh1,
                 const float* __restrict__ Wlin, const float* __restrict__ blin,
                 float* __restrict__ out)
{
    extern __shared__ float sm[];
    float* h1seq = sm + OFF_H1SEQ;
    float* zbuf  = sm + OFF_ZBUF;
    float* hs    = sm + OFF_HS;
    ulonglong2* xch  = reinterpret_cast<ulonglong2*>(sm + OFF_XCH);
    float4*     actx = reinterpret_cast<float4*>(sm + OFF_ACTX);
    float* wlin  = sm + OFF_WLIN;
    float* blin_s= sm + OFF_BLIN;

    const int tid = threadIdx.x;
    const int u   = tid & 63;          // unit
    const int ks  = tid >> 6;          // K-slice / bucket
    const int rg  = ks >> 2;           // 0: owns i,f rows; 1: owns g,o rows
    const int pp  = ks & 3;            // owned e-pair (for its rowgroup)
    const int e0  = blockIdx.x * EE;

    // rows whose final value this thread owns after combine
    const int r0 = u + (rg ? 2 * HID : 0);
    const int r1 = u + HID + (rg ? 2 * HID : 0);

    // init
    for (int idx = tid; idx < K0P * ES; idx += NT) zbuf[idx] = 0.0f;
    for (int idx = tid; idx < HID * ES; idx += NT) hs[idx] = 0.0f;
    for (int idx = tid; idx < OUTD * HID; idx += NT) wlin[idx] = Wlin[idx];
    if (tid < OUTD) blin_s[tid] = blin[tid];
    if (tid < IND * EE) {    // stage x(t=0)
        int k = tid >> 3, e = tid & 7;
        zbuf[k * ES + e] = x[(size_t)(e0 + e) * (TT * IND) + k];
    }

    float c0 = 0.0f, c1 = 0.0f;

    // ================= Layer 0 =================
    {
        float w0[KSL0], w1[KSL0], w2[KSL0], w3[KSL0];
#pragma unroll
        for (int i = 0; i < KSL0; i++) {
            int col = ks * KSL0 + i;
            float v0, v1, v2, v3;
            if (col < IND) {
                v0 = Wih0[u * IND + col];
                v1 = Wih0[(u + HID) * IND + col];
                v2 = Wih0[(u + 2 * HID) * IND + col];
                v3 = Wih0[(u + 3 * HID) * IND + col];
            } else if (col < IND + HID) {
                int ch = col - IND;
                v0 = Whh0[u * HID + ch];
                v1 = Whh0[(u + HID) * HID + ch];
                v2 = Whh0[(u + 2 * HID) * HID + ch];
                v3 = Whh0[(u + 3 * HID) * HID + ch];
            } else {
                v0 = v1 = v2 = v3 = 0.0f;
            }
            w0[i] = v0; w1[i] = v1; w2[i] = v2; w3[i] = v3;
        }
        const u64 biasP0 = splat2(bih0[r0] + bhh0[r0]);
        const u64 biasP1 = splat2(bih0[r1] + bhh0[r1]);
        const float* zbase = zbuf + ks * KSL0 * ES;

        __syncthreads();

#pragma unroll 1
        for (int t = 0; t < TT; t++) {
            u64 a0[4], a1[4], a2[4], a3[4];
#pragma unroll
            for (int i = 0; i < 4; i++) { a0[i] = 0; a1[i] = 0; a2[i] = 0; a3[i] = 0; }

            gate_partial<KSL0>(zbase, w0, w1, w2, w3, a0, a1, a2, a3);

            exchange_update(xch, actx, a0, a1, a2, a3, u, ks, biasP0, biasP1,
                            c0, c1,
                            zbuf + (IND + u) * ES,
                            h1seq + (t * HID + u) * ES, pp);

            // rg1 threads stage x(t+1) while rg0 updates cells
            if (rg == 1 && t + 1 < TT) {
                int idx = (ks - 4) * 64 + u;       // 0..255
                int k = idx >> 3, e = idx & 7;
                if (k < IND)
                    zbuf[k * ES + e] =
                        x[(size_t)(e0 + e) * (TT * IND) + (t + 1) * IND + k];
            }
            __syncthreads();
        }
    }

    // reset for layer 1
    c0 = 0.0f; c1 = 0.0f;
    for (int idx = tid; idx < HID * ES; idx += NT) hs[idx] = 0.0f;

    // ================= Layer 1 =================
    {
        // K=128: slices 0..3 -> Wih1 cols (operand h1seq[t]); 4..7 -> Whh1 (operand hs)
        const float* Wsel = (ks < 4) ? Wih1 : Whh1;
        const int koff = (ks & 3) * KSL1;
        float w0[KSL1], w1[KSL1], w2[KSL1], w3[KSL1];
#pragma unroll
        for (int i = 0; i < KSL1; i++) {
            w0[i] = Wsel[u * HID + koff + i];
            w1[i] = Wsel[(u + HID) * HID + koff + i];
            w2[i] = Wsel[(u + 2 * HID) * HID + koff + i];
            w3[i] = Wsel[(u + 3 * HID) * HID + koff + i];
        }
        const u64 biasP0 = splat2(bih1[r0] + bhh1[r0]);
        const u64 biasP1 = splat2(bih1[r1] + bhh1[r1]);
        const float* hbase = hs + (ks & 3) * KSL1 * ES;

        __syncthreads();

#pragma unroll 1
        for (int t = 0; t < TT; t++) {
            const float* base = (ks < 4) ? (h1seq + (t * HID + koff) * ES) : hbase;

            u64 a0[4], a1[4], a2[4], a3[4];
#pragma unroll
            for (int i = 0; i < 4; i++) { a0[i] = 0; a1[i] = 0; a2[i] = 0; a3[i] = 0; }

            gate_partial<KSL1>(base, w0, w1, w2, w3, a0, a1, a2, a3);

            exchange_update(xch, actx, a0, a1, a2, a3, u, ks, biasP0, biasP1,
                            c0, c1,
                            hs + u * ES, nullptr, pp);
            __syncthreads();
        }
    }

    // ================= Linear head =================
    if (tid < OUTD * EE) {
        int e = tid & (EE - 1);
        int o = tid >> 3;
        float s = blin_s[o];
#pragma unroll
        for (int k = 0; k < HID; k++)
            s += wlin[o * HID + k] * hs[k * ES + e];
        out[(size_t)(e0 + e) * OUTD + o] = s;
    }
}

extern "C" void kernel_launch(void* const* d_in, const int* in_sizes, int n_in,
                              void* d_out, int out_size)
{
    const float* x    = (const float*)d_in[0];
    const float* Wih0 = (const float*)d_in[1];
    const float* Whh0 = (const float*)d_in[2];
    const float* bih0 = (const float*)d_in[3];
    const float* bhh0 = (const float*)d_in[4];
    const float* Wih1 = (const float*)d_in[5];
    const float* Whh1 = (const float*)d_in[6];
    const float* bih1 = (const float*)d_in[7];
    const float* bhh1 = (const float*)d_in[8];
    const float* Wlin = (const float*)d_in[9];
    const float* blin = (const float*)d_in[10];
    float* out = (float*)d_out;

    int B = in_sizes[0] / (TT * IND);   // 16384
    int grid = B / EE;                  // 2048

    cudaFuncSetAttribute(rnn_fused_kernel,
                         cudaFuncAttributeMaxDynamicSharedMemorySize, SMEM_BYTES);
    rnn_fused_kernel<<<grid, NT, SMEM_BYTES>>>(
        x, Wih0, Whh0, bih0, bhh0, Wih1, Whh1, bih1, bhh1, Wlin, blin, out);
}

// round 8
// speedup vs baseline: 1.8753x; 1.8753x over previous
#include <cuda_runtime.h>
#include <cstdint>

#define TT   28
#define IND  28
#define HID  64
#define EE   16
#define ES   20        // padded operand row stride (floats)
#define OUTD 10
#define NT   256
#define K0   92        // layer0 K (28 x + 64 h)
#define K0H  46        // layer0 K-half
#define K1H  64        // layer1 K-half

// Shared memory (floats):
//  h1seq [TT][HID][ES] = 35840
//  zbuf  [92][ES]      =  1840   (x rows 0..27, h0 rows 28..91)
//  hs    [HID][ES]     =  1280
//  xch   ulonglong2[8*128] = 4096 floats (2 owners x 4 chunks x 128 p)
//  actx  [64][36]      =  2304
//  wlin 640, blin 16      -> total 46016 floats = 184 KB
#define OFF_H1SEQ 0
#define OFF_ZBUF  (OFF_H1SEQ + TT*HID*ES)
#define OFF_HS    (OFF_ZBUF + K0*ES)
#define OFF_XCH   (OFF_HS + HID*ES)
#define OFF_ACTX  (OFF_XCH + 8*128*4)
#define OFF_WLIN  (OFF_ACTX + 64*36)
#define OFF_BLIN  (OFF_WLIN + OUTD*HID)
#define SMEM_FLOATS (OFF_BLIN + 16)
#define SMEM_BYTES  (SMEM_FLOATS * 4)

typedef unsigned long long u64;

__device__ __forceinline__ u64 splat2(float w) {
    u64 r; asm("mov.b64 %0, {%1, %1};" : "=l"(r) : "f"(w)); return r;
}
__device__ __forceinline__ void ffma2(u64& d, u64 a, u64 b) {
    asm("fma.rn.f32x2 %0, %1, %2, %0;" : "+l"(d) : "l"(a), "l"(b));
}
__device__ __forceinline__ void fadd2(u64& d, u64 a) {
    asm("add.rn.f32x2 %0, %1, %0;" : "+l"(d) : "l"(a));
}
__device__ __forceinline__ float2 unpack2(u64 v) {
    float2 f; asm("mov.b64 {%0, %1}, %2;" : "=f"(f.x), "=f"(f.y) : "l"(v)); return f;
}
__device__ __forceinline__ float tanhfast(float x) {
    float r; asm("tanh.approx.f32 %0, %1;" : "=f"(r) : "f"(x)); return r;
}
__device__ __forceinline__ float sigfast(float x) {
    return fmaf(0.5f, tanhfast(0.5f * x), 0.5f);
}

// Gate partial: 2 gate rows (A=row p, B=row p+128), 16 batch elems, NK k-steps.
// Per k: 4 broadcast LDS.128 + 2 splat + 16 FFMA2.
template<int NK>
__device__ __forceinline__ void gate2(const float* __restrict__ base,
                                      const float* wA, const float* wB,
                                      u64 aA[8], u64 aB[8])
{
#pragma unroll
    for (int k = 0; k < NK; k++) {
        const ulonglong2* ptr = reinterpret_cast<const ulonglong2*>(base + k * ES);
        ulonglong2 q0 = ptr[0], q1 = ptr[1], q2 = ptr[2], q3 = ptr[3];
        u64 wa = splat2(wA[k]);
        u64 wb = splat2(wB[k]);
        ffma2(aA[0], q0.x, wa); ffma2(aB[0], q0.x, wb);
        ffma2(aA[1], q0.y, wa); ffma2(aB[1], q0.y, wb);
        ffma2(aA[2], q1.x, wa); ffma2(aB[2], q1.x, wb);
        ffma2(aA[3], q1.y, wa); ffma2(aB[3], q1.y, wb);
        ffma2(aA[4], q2.x, wa); ffma2(aB[4], q2.x, wb);
        ffma2(aA[5], q2.y, wa); ffma2(aB[5], q2.y, wb);
        ffma2(aA[6], q3.x, wa); ffma2(aB[6], q3.x, wb);
        ffma2(aA[7], q3.y, wa); ffma2(aB[7], q3.y, wb);
    }
}

__global__ void __launch_bounds__(NT, 1)
rnn_fused_kernel(const float* __restrict__ x,
                 const float* __restrict__ Wih0, const float* __restrict__ Whh0,
                 const float* __restrict__ bih0, const float* __restrict__ bhh0,
                 const float* __restrict__ Wih1, const float* __restrict__ Whh1,
                 const float* __restrict__ bih1, const float* __restrict__ bhh1,
                 const float* __restrict__ Wlin, const float* __restrict__ blin,
                 float* __restrict__ out)
{
    extern __shared__ float sm[];
    float* h1seq = sm + OFF_H1SEQ;
    float* zbuf  = sm + OFF_ZBUF;          // x rows [0,28) + h0 rows [28,92)
    float* hs    = sm + OFF_HS;
    ulonglong2* xch = reinterpret_cast<ulonglong2*>(sm + OFF_XCH);
    float* actx  = sm + OFF_ACTX;
    float* wlin  = sm + OFF_WLIN;
    float* blin_s= sm + OFF_BLIN;

    const int tid = threadIdx.x;
    const int p   = tid & 127;             // row pair: rows (p, p+128)
    const int ks  = tid >> 7;              // K-half / owned e-half
    const int u   = p & 63;                // unit
    const bool ig = (p < 64);              // true: owns (i,g); false: (f,o)
    const int e0  = blockIdx.x * EE;
    const int fb  = 1 - ks;                // foreign bucket

    // init
    for (int idx = tid; idx < K0 * ES; idx += NT) zbuf[idx] = 0.0f;
    for (int idx = tid; idx < HID * ES; idx += NT) hs[idx] = 0.0f;
    for (int idx = tid; idx < OUTD * HID; idx += NT) wlin[idx] = Wlin[idx];
    if (tid < OUTD) blin_s[tid] = blin[tid];
    for (int i = tid; i < IND * EE; i += NT) {     // stage x(t=0)
        int e = i / IND, k = i % IND;
        zbuf[k * ES + e] = x[(size_t)(e0 + e) * (TT * IND) + k];
    }

    float c8[8];
#pragma unroll
    for (int q = 0; q < 8; q++) c8[q] = 0.0f;

    // ================= Layer 0 =================
    {
        float wA[K0H], wB[K0H];
#pragma unroll
        for (int i = 0; i < K0H; i++) {
            int cidx = ks * K0H + i;
            if (cidx < IND) {
                wA[i] = Wih0[p * IND + cidx];
                wB[i] = Wih0[(p + 128) * IND + cidx];
            } else {
                wA[i] = Whh0[p * HID + (cidx - IND)];
                wB[i] = Whh0[(p + 128) * HID + (cidx - IND)];
            }
        }
        const u64 biasA = splat2(bih0[p] + bhh0[p]);
        const u64 biasB = splat2(bih0[p + 128] + bhh0[p + 128]);
        const float* zbase = zbuf + ks * K0H * ES;

        __syncthreads();

#pragma unroll 1
        for (int t = 0; t < TT; t++) {
            u64 aA[8], aB[8];
#pragma unroll
            for (int i = 0; i < 8; i++) { aA[i] = 0ULL; aB[i] = 0ULL; }

            gate2<K0H>(zbase, wA, wB, aA, aB);

            // ship foreign e-half (chunked, lane-consecutive 16B)
            xch[(fb * 4 + 0) * 128 + p] = make_ulonglong2(aA[4 * fb],     aA[4 * fb + 1]);
            xch[(fb * 4 + 1) * 128 + p] = make_ulonglong2(aA[4 * fb + 2], aA[4 * fb + 3]);
            xch[(fb * 4 + 2) * 128 + p] = make_ulonglong2(aB[4 * fb],     aB[4 * fb + 1]);
            xch[(fb * 4 + 3) * 128 + p] = make_ulonglong2(aB[4 * fb + 2], aB[4 * fb + 3]);
            __syncthreads();

            // combine own half + bias
            u64 sA0 = aA[4 * ks], sA1 = aA[4 * ks + 1], sA2 = aA[4 * ks + 2], sA3 = aA[4 * ks + 3];
            u64 sB0 = aB[4 * ks], sB1 = aB[4 * ks + 1], sB2 = aB[4 * ks + 2], sB3 = aB[4 * ks + 3];
            {
                ulonglong2 v0 = xch[(ks * 4 + 0) * 128 + p];
                ulonglong2 v1 = xch[(ks * 4 + 1) * 128 + p];
                ulonglong2 v2 = xch[(ks * 4 + 2) * 128 + p];
                ulonglong2 v3 = xch[(ks * 4 + 3) * 128 + p];
                fadd2(sA0, v0.x); fadd2(sA1, v0.y); fadd2(sA2, v1.x); fadd2(sA3, v1.y);
                fadd2(sB0, v2.x); fadd2(sB1, v2.y); fadd2(sB2, v3.x); fadd2(sB3, v3.y);
            }
            fadd2(sA0, biasA); fadd2(sA1, biasA); fadd2(sA2, biasA); fadd2(sA3, biasA);
            fadd2(sB0, biasB); fadd2(sB1, biasB); fadd2(sB2, biasB); fadd2(sB3, biasB);

            float2 vA[4] = {unpack2(sA0), unpack2(sA1), unpack2(sA2), unpack2(sA3)};
            float2 vB[4] = {unpack2(sB0), unpack2(sB1), unpack2(sB2), unpack2(sB3)};

            float iv[8], gv[8];
            if (ig) {
                // rows: i (p), g (p+128) — keep in registers
#pragma unroll
                for (int q = 0; q < 4; q++) {
                    iv[2 * q] = sigfast(vA[q].x);  iv[2 * q + 1] = sigfast(vA[q].y);
                    gv[2 * q] = tanhfast(vB[q].x); gv[2 * q + 1] = tanhfast(vB[q].y);
                }
            } else {
                // rows: f (p), o (p+128) — activate and export
                float* ab = actx + u * 36 + ks * 16;
                float4 f0, f1, o0, o1;
                f0 = make_float4(sigfast(vA[0].x), sigfast(vA[0].y), sigfast(vA[1].x), sigfast(vA[1].y));
                f1 = make_float4(sigfast(vA[2].x), sigfast(vA[2].y), sigfast(vA[3].x), sigfast(vA[3].y));
                o0 = make_float4(sigfast(vB[0].x), sigfast(vB[0].y), sigfast(vB[1].x), sigfast(vB[1].y));
                o1 = make_float4(sigfast(vB[2].x), sigfast(vB[2].y), sigfast(vB[3].x), sigfast(vB[3].y));
                *reinterpret_cast<float4*>(ab)      = f0;
                *reinterpret_cast<float4*>(ab + 4)  = f1;
                *reinterpret_cast<float4*>(ab + 8)  = o0;
                *reinterpret_cast<float4*>(ab + 12) = o1;
            }
            __syncthreads();

            if (ig) {
                const float* ab = actx + u * 36 + ks * 16;
                float h[8];
#pragma unroll
                for (int q = 0; q < 8; q++) {
                    float fg = ab[q];
                    float og = ab[8 + q];
                    c8[q] = fg * c8[q] + iv[q] * gv[q];
                    h[q] = og * tanhfast(c8[q]);
                }
                float* d0 = zbuf + (IND + u) * ES + 8 * ks;
                float* d1 = h1seq + (t * HID + u) * ES + 8 * ks;
                float4 h0 = make_float4(h[0], h[1], h[2], h[3]);
                float4 h1 = make_float4(h[4], h[5], h[6], h[7]);
                *reinterpret_cast<float4*>(d0)     = h0;
                *reinterpret_cast<float4*>(d0 + 4) = h1;
                *reinterpret_cast<float4*>(d1)     = h0;
                *reinterpret_cast<float4*>(d1 + 4) = h1;
            } else if (t + 1 < TT) {
                // (f,o) threads stage x(t+1): 128 threads, 448 floats
                int idx = (p - 64) + 64 * ks;
#pragma unroll
                for (int i2 = idx; i2 < IND * EE; i2 += 128) {
                    int e = i2 / IND, k = i2 % IND;
                    zbuf[k * ES + e] = x[(size_t)(e0 + e) * (TT * IND) + (t + 1) * IND + k];
                }
            }
            __syncthreads();
        }
    }

    // reset cell state for layer 1 (hs already zero)
#pragma unroll
    for (int q = 0; q < 8; q++) c8[q] = 0.0f;

    // ================= Layer 1 =================
    {
        // K=128: ks=0 -> Wih1 (operand h1seq[t]); ks=1 -> Whh1 (operand hs)
        const float* Wsel = ks ? Whh1 : Wih1;
        float wA[K1H], wB[K1H];
#pragma unroll
        for (int i = 0; i < K1H; i++) {
            wA[i] = Wsel[p * HID + i];
            wB[i] = Wsel[(p + 128) * HID + i];
        }
        const u64 biasA = splat2(bih1[p] + bhh1[p]);
        const u64 biasB = splat2(bih1[p + 128] + bhh1[p + 128]);

        __syncthreads();

#pragma unroll 1
        for (int t = 0; t < TT; t++) {
            const float* base = ks ? hs : (h1seq + t * HID * ES);

            u64 aA[8], aB[8];
#pragma unroll
            for (int i = 0; i < 8; i++) { aA[i] = 0ULL; aB[i] = 0ULL; }

            gate2<K1H>(base, wA, wB, aA, aB);

            xch[(fb * 4 + 0) * 128 + p] = make_ulonglong2(aA[4 * fb],     aA[4 * fb + 1]);
            xch[(fb * 4 + 1) * 128 + p] = make_ulonglong2(aA[4 * fb + 2], aA[4 * fb + 3]);
            xch[(fb * 4 + 2) * 128 + p] = make_ulonglong2(aB[4 * fb],     aB[4 * fb + 1]);
            xch[(fb * 4 + 3) * 128 + p] = make_ulonglong2(aB[4 * fb + 2], aB[4 * fb + 3]);
            __syncthreads();

            u64 sA0 = aA[4 * ks], sA1 = aA[4 * ks + 1], sA2 = aA[4 * ks + 2], sA3 = aA[4 * ks + 3];
            u64 sB0 = aB[4 * ks], sB1 = aB[4 * ks + 1], sB2 = aB[4 * ks + 2], sB3 = aB[4 * ks + 3];
            {
                ulonglong2 v0 = xch[(ks * 4 + 0) * 128 + p];
                ulonglong2 v1 = xch[(ks * 4 + 1) * 128 + p];
                ulonglong2 v2 = xch[(ks * 4 + 2) * 128 + p];
                ulonglong2 v3 = xch[(ks * 4 + 3) * 128 + p];
                fadd2(sA0, v0.x); fadd2(sA1, v0.y); fadd2(sA2, v1.x); fadd2(sA3, v1.y);
                fadd2(sB0, v2.x); fadd2(sB1, v2.y); fadd2(sB2, v3.x); fadd2(sB3, v3.y);
            }
            fadd2(sA0, biasA); fadd2(sA1, biasA); fadd2(sA2, biasA); fadd2(sA3, biasA);
            fadd2(sB0, biasB); fadd2(sB1, biasB); fadd2(sB2, biasB); fadd2(sB3, biasB);

            float2 vA[4] = {unpack2(sA0), unpack2(sA1), unpack2(sA2), unpack2(sA3)};
            float2 vB[4] = {unpack2(sB0), unpack2(sB1), unpack2(sB2), unpack2(sB3)};

            float iv[8], gv[8];
            if (ig) {
#pragma unroll
                for (int q = 0; q < 4; q++) {
                    iv[2 * q] = sigfast(vA[q].x);  iv[2 * q + 1] = sigfast(vA[q].y);
                    gv[2 * q] = tanhfast(vB[q].x); gv[2 * q + 1] = tanhfast(vB[q].y);
                }
            } else {
                float* ab = actx + u * 36 + ks * 16;
                float4 f0 = make_float4(sigfast(vA[0].x), sigfast(vA[0].y), sigfast(vA[1].x), sigfast(vA[1].y));
                float4 f1 = make_float4(sigfast(vA[2].x), sigfast(vA[2].y), sigfast(vA[3].x), sigfast(vA[3].y));
                float4 o0 = make_float4(sigfast(vB[0].x), sigfast(vB[0].y), sigfast(vB[1].x), sigfast(vB[1].y));
                float4 o1 = make_float4(sigfast(vB[2].x), sigfast(vB[2].y), sigfast(vB[3].x), sigfast(vB[3].y));
                *reinterpret_cast<float4*>(ab)      = f0;
                *reinterpret_cast<float4*>(ab + 4)  = f1;
                *reinterpret_cast<float4*>(ab + 8)  = o0;
                *reinterpret_cast<float4*>(ab + 12) = o1;
            }
            __syncthreads();

            if (ig) {
                const float* ab = actx + u * 36 + ks * 16;
                float h[8];
#pragma unroll
                for (int q = 0; q < 8; q++) {
                    float fg = ab[q];
                    float og = ab[8 + q];
                    c8[q] = fg * c8[q] + iv[q] * gv[q];
                    h[q] = og * tanhfast(c8[q]);
                }
                float* d0 = hs + u * ES + 8 * ks;
                *reinterpret_cast<float4*>(d0)     = make_float4(h[0], h[1], h[2], h[3]);
                *reinterpret_cast<float4*>(d0 + 4) = make_float4(h[4], h[5], h[6], h[7]);
            }
            __syncthreads();
        }
    }

    // ================= Linear head =================
    if (tid < OUTD * EE) {
        int e = tid & (EE - 1);
        int o = tid >> 4;
        float s = blin_s[o];
#pragma unroll
        for (int k = 0; k < HID; k++)
            s += wlin[o * HID + k] * hs[k * ES + e];
        out[(size_t)(e0 + e) * OUTD + o] = s;
    }
}

extern "C" void kernel_launch(void* const* d_in, const int* in_sizes, int n_in,
                              void* d_out, int out_size)
{
    const float* x    = (const float*)d_in[0];
    const float* Wih0 = (const float*)d_in[1];
    const float* Whh0 = (const float*)d_in[2];
    const float* bih0 = (const float*)d_in[3];
    const float* bhh0 = (const float*)d_in[4];
    const float* Wih1 = (const float*)d_in[5];
    const float* Whh1 = (const float*)d_in[6];
    const float* bih1 = (const float*)d_in[7];
    const float* bhh1 = (const float*)d_in[8];
    const float* Wlin = (const float*)d_in[9];
    const float* blin = (const float*)d_in[10];
    float* out = (float*)d_out;

    int B = in_sizes[0] / (TT * IND);   // 16384
    int grid = B / EE;                  // 1024

    cudaFuncSetAttribute(rnn_fused_kernel,
                         cudaFuncAttributeMaxDynamicSharedMemorySize, SMEM_BYTES);
    rnn_fused_kernel<<<grid, NT, SMEM_BYTES>>>(
        x, Wih0, Whh0, bih0, bhh0, Wih1, Whh1, bih1, bhh1, Wlin, blin, out);
}

// round 9
// speedup vs baseline: 2.3272x; 1.2410x over previous
#include <cuda_runtime.h>
#include <cstdint>

#define TT   28
#define IND  28
#define HID  64
#define EE   16
#define ES   20        // padded operand row stride (floats)
#define OUTD 10
#define NT   256
#define K0   92        // layer0 K (28 x + 64 h)
#define K0H  46        // layer0 K-half
#define K1H  64        // layer1 K-half

// Shared memory (floats):
//  h1seq [TT][HID][ES] = 35840
//  zbuf  [92][ES]      =  1840   (x rows 0..27, h0 rows 28..91)
//  hs    [HID][ES]     =  1280
//  xch   ulonglong2[8*128] = 4096 floats
//  actx  [64][36]      =  2304
//  wlin 640, blin 16
#define OFF_H1SEQ 0
#define OFF_ZBUF  (OFF_H1SEQ + TT*HID*ES)
#define OFF_HS    (OFF_ZBUF + K0*ES)
#define OFF_XCH   (OFF_HS + HID*ES)
#define OFF_ACTX  (OFF_XCH + 8*128*4)
#define OFF_WLIN  (OFF_ACTX + 64*36)
#define OFF_BLIN  (OFF_WLIN + OUTD*HID)
#define SMEM_FLOATS (OFF_BLIN + 16)
#define SMEM_BYTES  (SMEM_FLOATS * 4)

typedef unsigned long long u64;

__device__ __forceinline__ u64 splat2(float w) {
    u64 r; asm("mov.b64 %0, {%1, %1};" : "=l"(r) : "f"(w)); return r;
}
__device__ __forceinline__ void ffma2(u64& d, u64 a, u64 b) {
    asm("fma.rn.f32x2 %0, %1, %2, %0;" : "+l"(d) : "l"(a), "l"(b));
}
__device__ __forceinline__ void fadd2(u64& d, u64 a) {
    asm("add.rn.f32x2 %0, %1, %0;" : "+l"(d) : "l"(a));
}
__device__ __forceinline__ float2 unpack2(u64 v) {
    float2 f; asm("mov.b64 {%0, %1}, %2;" : "=f"(f.x), "=f"(f.y) : "l"(v)); return f;
}
__device__ __forceinline__ float tanhfast(float x) {
    float r; asm("tanh.approx.f32 %0, %1;" : "=f"(r) : "f"(x)); return r;
}
__device__ __forceinline__ float sigfast(float x) {
    return fmaf(0.5f, tanhfast(0.5f * x), 0.5f);
}

// Gate partial over ONE e-half: 2 gate rows (A=row p, B=row p+128), 8 batch elems.
// Per k: 2 broadcast LDS.128 + 2 splat + 8 FFMA2. Only 8 u64 accs live.
template<int NK>
__device__ __forceinline__ void gate_half(const float* __restrict__ base, int eoff,
                                          const float* wA, const float* wB,
                                          u64 aA[4], u64 aB[4])
{
#pragma unroll
    for (int k = 0; k < NK; k++) {
        const ulonglong2* ptr = reinterpret_cast<const ulonglong2*>(base + k * ES + eoff);
        ulonglong2 q0 = ptr[0], q1 = ptr[1];
        u64 wa = splat2(wA[k]);
        u64 wb = splat2(wB[k]);
        ffma2(aA[0], q0.x, wa); ffma2(aB[0], q0.x, wb);
        ffma2(aA[1], q0.y, wa); ffma2(aB[1], q0.y, wb);
        ffma2(aA[2], q1.x, wa); ffma2(aB[2], q1.x, wb);
        ffma2(aA[3], q1.y, wa); ffma2(aB[3], q1.y, wb);
    }
}

__global__ void __launch_bounds__(NT, 1)
rnn_fused_kernel(const float* __restrict__ x,
                 const float* __restrict__ Wih0, const float* __restrict__ Whh0,
                 const float* __restrict__ bih0, const float* __restrict__ bhh0,
                 const float* __restrict__ Wih1, const float* __restrict__ Whh1,
                 const float* __restrict__ bih1, const float* __restrict__ bhh1,
                 const float* __restrict__ Wlin, const float* __restrict__ blin,
                 float* __restrict__ out)
{
    extern __shared__ float sm[];
    float* h1seq = sm + OFF_H1SEQ;
    float* zbuf  = sm + OFF_ZBUF;          // x rows [0,28) + h0 rows [28,92)
    float* hs    = sm + OFF_HS;
    ulonglong2* xch = reinterpret_cast<ulonglong2*>(sm + OFF_XCH);
    float* actx  = sm + OFF_ACTX;
    float* wlin  = sm + OFF_WLIN;
    float* blin_s= sm + OFF_BLIN;

    const int tid = threadIdx.x;
    const int p   = tid & 127;             // row pair: rows (p, p+128)
    const int ks  = tid >> 7;              // K-half / owned e-half
    const int u   = p & 63;                // unit
    const bool ig = (p < 64);              // true: owns (i,g); false: (f,o)
    const int e0  = blockIdx.x * EE;
    const int fb  = 1 - ks;                // foreign e-half

    // init
    for (int idx = tid; idx < K0 * ES; idx += NT) zbuf[idx] = 0.0f;
    for (int idx = tid; idx < HID * ES; idx += NT) hs[idx] = 0.0f;
    for (int idx = tid; idx < OUTD * HID; idx += NT) wlin[idx] = Wlin[idx];
    if (tid < OUTD) blin_s[tid] = blin[tid];
    for (int i = tid; i < IND * EE; i += NT) {     // stage x(t=0)
        int e = i / IND, k = i % IND;
        zbuf[k * ES + e] = x[(size_t)(e0 + e) * (TT * IND) + k];
    }

    float c8[8];
#pragma unroll
    for (int q = 0; q < 8; q++) c8[q] = 0.0f;

    // ================= Layer 0 =================
    {
        float wA[K0H], wB[K0H];
#pragma unroll
        for (int i = 0; i < K0H; i++) {
            int cidx = ks * K0H + i;
            if (cidx < IND) {
                wA[i] = Wih0[p * IND + cidx];
                wB[i] = Wih0[(p + 128) * IND + cidx];
            } else {
                wA[i] = Whh0[p * HID + (cidx - IND)];
                wB[i] = Whh0[(p + 128) * HID + (cidx - IND)];
            }
        }
        const u64 biasA = splat2(bih0[p] + bhh0[p]);
        const u64 biasB = splat2(bih0[p + 128] + bhh0[p + 128]);
        const float* zbase = zbuf + ks * K0H * ES;

        __syncthreads();

#pragma unroll 1
        for (int t = 0; t < TT; t++) {
            // pass 1: foreign e-half, ship immediately
            {
                u64 fA[4] = {0ULL, 0ULL, 0ULL, 0ULL};
                u64 fB[4] = {0ULL, 0ULL, 0ULL, 0ULL};
                gate_half<K0H>(zbase, 8 * fb, wA, wB, fA, fB);
                xch[(fb * 4 + 0) * 128 + p] = make_ulonglong2(fA[0], fA[1]);
                xch[(fb * 4 + 1) * 128 + p] = make_ulonglong2(fA[2], fA[3]);
                xch[(fb * 4 + 2) * 128 + p] = make_ulonglong2(fB[0], fB[1]);
                xch[(fb * 4 + 3) * 128 + p] = make_ulonglong2(fB[2], fB[3]);
            }
            // pass 2: own e-half (bias pre-loaded)
            u64 oA[4] = {biasA, biasA, biasA, biasA};
            u64 oB[4] = {biasB, biasB, biasB, biasB};
            gate_half<K0H>(zbase, 8 * ks, wA, wB, oA, oB);
            __syncthreads();

            {
                ulonglong2 v0 = xch[(ks * 4 + 0) * 128 + p];
                ulonglong2 v1 = xch[(ks * 4 + 1) * 128 + p];
                ulonglong2 v2 = xch[(ks * 4 + 2) * 128 + p];
                ulonglong2 v3 = xch[(ks * 4 + 3) * 128 + p];
                fadd2(oA[0], v0.x); fadd2(oA[1], v0.y); fadd2(oA[2], v1.x); fadd2(oA[3], v1.y);
                fadd2(oB[0], v2.x); fadd2(oB[1], v2.y); fadd2(oB[2], v3.x); fadd2(oB[3], v3.y);
            }

            float2 vA[4] = {unpack2(oA[0]), unpack2(oA[1]), unpack2(oA[2]), unpack2(oA[3])};
            float2 vB[4] = {unpack2(oB[0]), unpack2(oB[1]), unpack2(oB[2]), unpack2(oB[3])};

            float iv[8], gv[8];
            if (ig) {
                // rows: i (p), g (p+128) — keep in registers
#pragma unroll
                for (int q = 0; q < 4; q++) {
                    iv[2 * q] = sigfast(vA[q].x);  iv[2 * q + 1] = sigfast(vA[q].y);
                    gv[2 * q] = tanhfast(vB[q].x); gv[2 * q + 1] = tanhfast(vB[q].y);
                }
            } else {
                // rows: f (p), o (p+128) — activate and export
                float* ab = actx + u * 36 + ks * 16;
                *reinterpret_cast<float4*>(ab)      = make_float4(sigfast(vA[0].x), sigfast(vA[0].y), sigfast(vA[1].x), sigfast(vA[1].y));
                *reinterpret_cast<float4*>(ab + 4)  = make_float4(sigfast(vA[2].x), sigfast(vA[2].y), sigfast(vA[3].x), sigfast(vA[3].y));
                *reinterpret_cast<float4*>(ab + 8)  = make_float4(sigfast(vB[0].x), sigfast(vB[0].y), sigfast(vB[1].x), sigfast(vB[1].y));
                *reinterpret_cast<float4*>(ab + 12) = make_float4(sigfast(vB[2].x), sigfast(vB[2].y), sigfast(vB[3].x), sigfast(vB[3].y));
            }
            __syncthreads();

            if (ig) {
                const float* ab = actx + u * 36 + ks * 16;
                float h[8];
#pragma unroll
                for (int q = 0; q < 8; q++) {
                    float fg = ab[q];
                    float og = ab[8 + q];
                    c8[q] = fg * c8[q] + iv[q] * gv[q];
                    h[q] = og * tanhfast(c8[q]);
                }
                float* d0 = zbuf + (IND + u) * ES + 8 * ks;
                float* d1 = h1seq + (t * HID + u) * ES + 8 * ks;
                float4 h0 = make_float4(h[0], h[1], h[2], h[3]);
                float4 h1 = make_float4(h[4], h[5], h[6], h[7]);
                *reinterpret_cast<float4*>(d0)     = h0;
                *reinterpret_cast<float4*>(d0 + 4) = h1;
                *reinterpret_cast<float4*>(d1)     = h0;
                *reinterpret_cast<float4*>(d1 + 4) = h1;
            } else if (t + 1 < TT) {
                // (f,o) threads stage x(t+1): 128 threads, 448 floats
                int idx = (p - 64) + 64 * ks;
#pragma unroll
                for (int i2 = idx; i2 < IND * EE; i2 += 128) {
                    int e = i2 / IND, k = i2 % IND;
                    zbuf[k * ES + e] = x[(size_t)(e0 + e) * (TT * IND) + (t + 1) * IND + k];
                }
            }
            __syncthreads();
        }
    }

    // reset cell state for layer 1
#pragma unroll
    for (int q = 0; q < 8; q++) c8[q] = 0.0f;

    // ================= Layer 1 =================
    {
        // K=128: ks=0 -> Wih1 (operand h1seq[t]); ks=1 -> Whh1 (operand hs)
        const float* Wsel = ks ? Whh1 : Wih1;
        float wA[K1H], wB[K1H];
#pragma unroll
        for (int i = 0; i < K1H; i++) {
            wA[i] = Wsel[p * HID + i];
            wB[i] = Wsel[(p + 128) * HID + i];
        }
        const u64 biasA = splat2(bih1[p] + bhh1[p]);
        const u64 biasB = splat2(bih1[p + 128] + bhh1[p + 128]);

        __syncthreads();

#pragma unroll 1
        for (int t = 0; t < TT; t++) {
            const float* base = ks ? hs : (h1seq + t * HID * ES);

            {
                u64 fA[4] = {0ULL, 0ULL, 0ULL, 0ULL};
                u64 fB[4] = {0ULL, 0ULL, 0ULL, 0ULL};
                gate_half<K1H>(base, 8 * fb, wA, wB, fA, fB);
                xch[(fb * 4 + 0) * 128 + p] = make_ulonglong2(fA[0], fA[1]);
                xch[(fb * 4 + 1) * 128 + p] = make_ulonglong2(fA[2], fA[3]);
                xch[(fb * 4 + 2) * 128 + p] = make_ulonglong2(fB[0], fB[1]);
                xch[(fb * 4 + 3) * 128 + p] = make_ulonglong2(fB[2], fB[3]);
            }
            u64 oA[4] = {biasA, biasA, biasA, biasA};
            u64 oB[4] = {biasB, biasB, biasB, biasB};
            gate_half<K1H>(base, 8 * ks, wA, wB, oA, oB);
            __syncthreads();

            {
                ulonglong2 v0 = xch[(ks * 4 + 0) * 128 + p];
                ulonglong2 v1 = xch[(ks * 4 + 1) * 128 + p];
                ulonglong2 v2 = xch[(ks * 4 + 2) * 128 + p];
                ulonglong2 v3 = xch[(ks * 4 + 3) * 128 + p];
                fadd2(oA[0], v0.x); fadd2(oA[1], v0.y); fadd2(oA[2], v1.x); fadd2(oA[3], v1.y);
                fadd2(oB[0], v2.x); fadd2(oB[1], v2.y); fadd2(oB[2], v3.x); fadd2(oB[3], v3.y);
            }

            float2 vA[4] = {unpack2(oA[0]), unpack2(oA[1]), unpack2(oA[2]), unpack2(oA[3])};
            float2 vB[4] = {unpack2(oB[0]), unpack2(oB[1]), unpack2(oB[2]), unpack2(oB[3])};

            float iv[8], gv[8];
            if (ig) {
#pragma unroll
                for (int q = 0; q < 4; q++) {
                    iv[2 * q] = sigfast(vA[q].x);  iv[2 * q + 1] = sigfast(vA[q].y);
                    gv[2 * q] = tanhfast(vB[q].x); gv[2 * q + 1] = tanhfast(vB[q].y);
                }
            } else {
                float* ab = actx + u * 36 + ks * 16;
                *reinterpret_cast<float4*>(ab)      = make_float4(sigfast(vA[0].x), sigfast(vA[0].y), sigfast(vA[1].x), sigfast(vA[1].y));
                *reinterpret_cast<float4*>(ab + 4)  = make_float4(sigfast(vA[2].x), sigfast(vA[2].y), sigfast(vA[3].x), sigfast(vA[3].y));
                *reinterpret_cast<float4*>(ab + 8)  = make_float4(sigfast(vB[0].x), sigfast(vB[0].y), sigfast(vB[1].x), sigfast(vB[1].y));
                *reinterpret_cast<float4*>(ab + 12) = make_float4(sigfast(vB[2].x), sigfast(vB[2].y), sigfast(vB[3].x), sigfast(vB[3].y));
            }
            __syncthreads();

            if (ig) {
                const float* ab = actx + u * 36 + ks * 16;
                float h[8];
#pragma unroll
                for (int q = 0; q < 8; q++) {
                    float fg = ab[q];
                    float og = ab[8 + q];
                    c8[q] = fg * c8[q] + iv[q] * gv[q];
                    h[q] = og * tanhfast(c8[q]);
                }
                float* d0 = hs + u * ES + 8 * ks;
                *reinterpret_cast<float4*>(d0)     = make_float4(h[0], h[1], h[2], h[3]);
                *reinterpret_cast<float4*>(d0 + 4) = make_float4(h[4], h[5], h[6], h[7]);
            }
            __syncthreads();
        }
    }

    // ================= Linear head =================
    if (tid < OUTD * EE) {
        int e = tid & (EE - 1);
        int o = tid >> 4;
        float s = blin_s[o];
#pragma unroll
        for (int k = 0; k < HID; k++)
            s += wlin[o * HID + k] * hs[k * ES + e];
        out[(size_t)(e0 + e) * OUTD + o] = s;
    }
}

extern "C" void kernel_launch(void* const* d_in, const int* in_sizes, int n_in,
                              void* d_out, int out_size)
{
    const float* x    = (const float*)d_in[0];
    const float* Wih0 = (const float*)d_in[1];
    const float* Whh0 = (const float*)d_in[2];
    const float* bih0 = (const float*)d_in[3];
    const float* bhh0 = (const float*)d_in[4];
    const float* Wih1 = (const float*)d_in[5];
    const float* Whh1 = (const float*)d_in[6];
    const float* bih1 = (const float*)d_in[7];
    const float* bhh1 = (const float*)d_in[8];
    const float* Wlin = (const float*)d_in[9];
    const float* blin = (const float*)d_in[10];
    float* out = (float*)d_out;

    int B = in_sizes[0] / (TT * IND);   // 16384
    int grid = B / EE;                  // 1024

    cudaFuncSetAttribute(rnn_fused_kernel,
                         cudaFuncAttributeMaxDynamicSharedMemorySize, SMEM_BYTES);
    rnn_fused_kernel<<<grid, NT, SMEM_BYTES>>>(
        x, Wih0, Whh0, bih0, bhh0, Wih1, Whh1, bih1, bhh1, Wlin, blin, out);
}

// round 10
// speedup vs baseline: 2.3394x; 1.0052x over previous
#include <cuda_runtime.h>
#include <cstdint>

#define TT   28
#define IND  28
#define HID  64
#define EE   16
#define ES   20        // padded operand row stride (floats)
#define OUTD 10
#define NT   256
#define K0   92        // layer0 K (28 x + 64 h)
#define K0H  46        // layer0 K-half
#define K1H  64        // layer1 K-half

// Shared memory (floats):
//  h1seq [TT][HID][ES] = 35840
//  zbuf  [92][ES]      =  1840   (x rows 0..27, h0 rows 28..91)
//  hs    [HID][ES]     =  1280
//  xch   ulonglong2[8*128] = 4096 floats
//  actx  [64][36]      =  2304
//  wlin 640, blin 16
#define OFF_H1SEQ 0
#define OFF_ZBUF  (OFF_H1SEQ + TT*HID*ES)
#define OFF_HS    (OFF_ZBUF + K0*ES)
#define OFF_XCH   (OFF_HS + HID*ES)
#define OFF_ACTX  (OFF_XCH + 8*128*4)
#define OFF_WLIN  (OFF_ACTX + 64*36)
#define OFF_BLIN  (OFF_WLIN + OUTD*HID)
#define SMEM_FLOATS (OFF_BLIN + 16)
#define SMEM_BYTES  (SMEM_FLOATS * 4)

typedef unsigned long long u64;

__device__ __forceinline__ u64 splat2(float w) {
    u64 r; asm("mov.b64 %0, {%1, %1};" : "=l"(r) : "f"(w)); return r;
}
__device__ __forceinline__ void ffma2(u64& d, u64 a, u64 b) {
    asm("fma.rn.f32x2 %0, %1, %2, %0;" : "+l"(d) : "l"(a), "l"(b));
}
__device__ __forceinline__ void fadd2(u64& d, u64 a) {
    asm("add.rn.f32x2 %0, %1, %0;" : "+l"(d) : "l"(a));
}
__device__ __forceinline__ float2 unpack2(u64 v) {
    float2 f; asm("mov.b64 {%0, %1}, %2;" : "=f"(f.x), "=f"(f.y) : "l"(v)); return f;
}
__device__ __forceinline__ float tanhfast(float x) {
    float r; asm("tanh.approx.f32 %0, %1;" : "=f"(r) : "f"(x)); return r;
}
__device__ __forceinline__ float sigfast(float x) {
    return fmaf(0.5f, tanhfast(0.5f * x), 0.5f);
}
__device__ __forceinline__ void barpair_sync(int id) {
    asm volatile("bar.sync %0, 64;" :: "r"(id) : "memory");
}
__device__ __forceinline__ void barpair_arrive(int id) {
    asm volatile("bar.arrive %0, 64;" :: "r"(id) : "memory");
}

// Gate partial over ONE e-half: 2 gate rows (A=row p, B=row p+128), 8 batch elems.
// Per k: 2 broadcast LDS.128 + 2 splat + 8 FFMA2. Only 8 u64 accs live.
template<int NK>
__device__ __forceinline__ void gate_half(const float* __restrict__ base, int eoff,
                                          const float* wA, const float* wB,
                                          u64 aA[4], u64 aB[4])
{
#pragma unroll
    for (int k = 0; k < NK; k++) {
        const ulonglong2* ptr = reinterpret_cast<const ulonglong2*>(base + k * ES + eoff);
        ulonglong2 q0 = ptr[0], q1 = ptr[1];
        u64 wa = splat2(wA[k]);
        u64 wb = splat2(wB[k]);
        ffma2(aA[0], q0.x, wa); ffma2(aB[0], q0.x, wb);
        ffma2(aA[1], q0.y, wa); ffma2(aB[1], q0.y, wb);
        ffma2(aA[2], q1.x, wa); ffma2(aB[2], q1.x, wb);
        ffma2(aA[3], q1.y, wa); ffma2(aB[3], q1.y, wb);
    }
}

__global__ void __launch_bounds__(NT, 1)
rnn_fused_kernel(const float* __restrict__ x,
                 const float* __restrict__ Wih0, const float* __restrict__ Whh0,
                 const float* __restrict__ bih0, const float* __restrict__ bhh0,
                 const float* __restrict__ Wih1, const float* __restrict__ Whh1,
                 const float* __restrict__ bih1, const float* __restrict__ bhh1,
                 const float* __restrict__ Wlin, const float* __restrict__ blin,
                 float* __restrict__ out)
{
    extern __shared__ float sm[];
    float* h1seq = sm + OFF_H1SEQ;
    float* zbuf  = sm + OFF_ZBUF;          // x rows [0,28) + h0 rows [28,92)
    float* hs    = sm + OFF_HS;
    ulonglong2* xch = reinterpret_cast<ulonglong2*>(sm + OFF_XCH);
    float* actx  = sm + OFF_ACTX;
    float* wlin  = sm + OFF_WLIN;
    float* blin_s= sm + OFF_BLIN;

    const int tid = threadIdx.x;
    const int p   = tid & 127;             // row pair: rows (p, p+128)
    const int ks  = tid >> 7;              // K-half / owned e-half
    const int u   = p & 63;                // unit
    const bool ig = (p < 64);              // true: owns (i,g); false: (f,o)
    const int e0  = blockIdx.x * EE;
    const int fb  = 1 - ks;                // foreign e-half
    const int w   = tid >> 5;              // warp id
    const int idA = 1 + (w & 3);           // pair (w, w+4): K-combine partners
    const int idB = 5 + (w & 1) + 2 * (w >> 2); // pairs (0,2),(1,3),(4,6),(5,7): actx

    // init
    for (int idx = tid; idx < K0 * ES; idx += NT) zbuf[idx] = 0.0f;
    for (int idx = tid; idx < HID * ES; idx += NT) hs[idx] = 0.0f;
    for (int idx = tid; idx < OUTD * HID; idx += NT) wlin[idx] = Wlin[idx];
    if (tid < OUTD) blin_s[tid] = blin[tid];
    for (int i = tid; i < IND * EE; i += NT) {     // stage x(t=0)
        int e = i / IND, k = i % IND;
        zbuf[k * ES + e] = x[(size_t)(e0 + e) * (TT * IND) + k];
    }

    float c8[8];
#pragma unroll
    for (int q = 0; q < 8; q++) c8[q] = 0.0f;

    // ================= Layer 0 =================
    {
        float wA[K0H], wB[K0H];
#pragma unroll
        for (int i = 0; i < K0H; i++) {
            int cidx = ks * K0H + i;
            if (cidx < IND) {
                wA[i] = Wih0[p * IND + cidx];
                wB[i] = Wih0[(p + 128) * IND + cidx];
            } else {
                wA[i] = Whh0[p * HID + (cidx - IND)];
                wB[i] = Whh0[(p + 128) * HID + (cidx - IND)];
            }
        }
        const u64 biasA = splat2(bih0[p] + bhh0[p]);
        const u64 biasB = splat2(bih0[p + 128] + bhh0[p + 128]);
        const float* zbase = zbuf + ks * K0H * ES;

        __syncthreads();

#pragma unroll 1
        for (int t = 0; t < TT; t++) {
            // pass 1: foreign e-half, ship immediately
            {
                u64 fA[4] = {0ULL, 0ULL, 0ULL, 0ULL};
                u64 fB[4] = {0ULL, 0ULL, 0ULL, 0ULL};
                gate_half<K0H>(zbase, 8 * fb, wA, wB, fA, fB);
                xch[(fb * 4 + 0) * 128 + p] = make_ulonglong2(fA[0], fA[1]);
                xch[(fb * 4 + 1) * 128 + p] = make_ulonglong2(fA[2], fA[3]);
                xch[(fb * 4 + 2) * 128 + p] = make_ulonglong2(fB[0], fB[1]);
                xch[(fb * 4 + 3) * 128 + p] = make_ulonglong2(fB[2], fB[3]);
            }
            // pass 2: own e-half (bias pre-loaded)
            u64 oA[4] = {biasA, biasA, biasA, biasA};
            u64 oB[4] = {biasB, biasB, biasB, biasB};
            gate_half<K0H>(zbase, 8 * ks, wA, wB, oA, oB);
            barpair_sync(idA);              // only partner (p, 1-ks) matters

            {
                ulonglong2 v0 = xch[(ks * 4 + 0) * 128 + p];
                ulonglong2 v1 = xch[(ks * 4 + 1) * 128 + p];
                ulonglong2 v2 = xch[(ks * 4 + 2) * 128 + p];
                ulonglong2 v3 = xch[(ks * 4 + 3) * 128 + p];
                fadd2(oA[0], v0.x); fadd2(oA[1], v0.y); fadd2(oA[2], v1.x); fadd2(oA[3], v1.y);
                fadd2(oB[0], v2.x); fadd2(oB[1], v2.y); fadd2(oB[2], v3.x); fadd2(oB[3], v3.y);
            }

            float2 vA[4] = {unpack2(oA[0]), unpack2(oA[1]), unpack2(oA[2]), unpack2(oA[3])};
            float2 vB[4] = {unpack2(oB[0]), unpack2(oB[1]), unpack2(oB[2]), unpack2(oB[3])};

            float iv[8], gv[8];
            if (ig) {
                // rows: i (p), g (p+128) — keep in registers
#pragma unroll
                for (int q = 0; q < 4; q++) {
                    iv[2 * q] = sigfast(vA[q].x);  iv[2 * q + 1] = sigfast(vA[q].y);
                    gv[2 * q] = tanhfast(vB[q].x); gv[2 * q + 1] = tanhfast(vB[q].y);
                }
            } else {
                // rows: f (p), o (p+128) — activate and export
                float* ab = actx + u * 36 + ks * 16;
                *reinterpret_cast<float4*>(ab)      = make_float4(sigfast(vA[0].x), sigfast(vA[0].y), sigfast(vA[1].x), sigfast(vA[1].y));
                *reinterpret_cast<float4*>(ab + 4)  = make_float4(sigfast(vA[2].x), sigfast(vA[2].y), sigfast(vA[3].x), sigfast(vA[3].y));
                *reinterpret_cast<float4*>(ab + 8)  = make_float4(sigfast(vB[0].x), sigfast(vB[0].y), sigfast(vB[1].x), sigfast(vB[1].y));
                *reinterpret_cast<float4*>(ab + 12) = make_float4(sigfast(vB[2].x), sigfast(vB[2].y), sigfast(vB[3].x), sigfast(vB[3].y));
            }
            // Full barrier in layer 0: fo threads overwrite zbuf x-rows below,
            // which are read by warps outside their B-pair during the passes.
            __syncthreads();

            if (ig) {
                const float* ab = actx + u * 36 + ks * 16;
                float h[8];
#pragma unroll
                for (int q = 0; q < 8; q++) {
                    float fg = ab[q];
                    float og = ab[8 + q];
                    c8[q] = fg * c8[q] + iv[q] * gv[q];
                    h[q] = og * tanhfast(c8[q]);
                }
                float* d0 = zbuf + (IND + u) * ES + 8 * ks;
                float* d1 = h1seq + (t * HID + u) * ES + 8 * ks;
                float4 h0 = make_float4(h[0], h[1], h[2], h[3]);
                float4 h1 = make_float4(h[4], h[5], h[6], h[7]);
                *reinterpret_cast<float4*>(d0)     = h0;
                *reinterpret_cast<float4*>(d0 + 4) = h1;
                *reinterpret_cast<float4*>(d1)     = h0;
                *reinterpret_cast<float4*>(d1 + 4) = h1;
            } else if (t + 1 < TT) {
                // (f,o) threads stage x(t+1): 128 threads, 448 floats
                int idx = (p - 64) + 64 * ks;
#pragma unroll
                for (int i2 = idx; i2 < IND * EE; i2 += 128) {
                    int e = i2 / IND, k = i2 % IND;
                    zbuf[k * ES + e] = x[(size_t)(e0 + e) * (TT * IND) + (t + 1) * IND + k];
                }
            }
            __syncthreads();
        }
    }

    // reset cell state for layer 1
#pragma unroll
    for (int q = 0; q < 8; q++) c8[q] = 0.0f;

    // ================= Layer 1 =================
    {
        // K=128: ks=0 -> Wih1 (operand h1seq[t]); ks=1 -> Whh1 (operand hs)
        const float* Wsel = ks ? Whh1 : Wih1;
        float wA[K1H], wB[K1H];
#pragma unroll
        for (int i = 0; i < K1H; i++) {
            wA[i] = Wsel[p * HID + i];
            wB[i] = Wsel[(p + 128) * HID + i];
        }
        const u64 biasA = splat2(bih1[p] + bhh1[p]);
        const u64 biasB = splat2(bih1[p + 128] + bhh1[p + 128]);

        __syncthreads();

#pragma unroll 1
        for (int t = 0; t < TT; t++) {
            const float* base = ks ? hs : (h1seq + t * HID * ES);

            {
                u64 fA[4] = {0ULL, 0ULL, 0ULL, 0ULL};
                u64 fB[4] = {0ULL, 0ULL, 0ULL, 0ULL};
                gate_half<K1H>(base, 8 * fb, wA, wB, fA, fB);
                xch[(fb * 4 + 0) * 128 + p] = make_ulonglong2(fA[0], fA[1]);
                xch[(fb * 4 + 1) * 128 + p] = make_ulonglong2(fA[2], fA[3]);
                xch[(fb * 4 + 2) * 128 + p] = make_ulonglong2(fB[0], fB[1]);
                xch[(fb * 4 + 3) * 128 + p] = make_ulonglong2(fB[2], fB[3]);
            }
            u64 oA[4] = {biasA, biasA, biasA, biasA};
            u64 oB[4] = {biasB, biasB, biasB, biasB};
            gate_half<K1H>(base, 8 * ks, wA, wB, oA, oB);
            barpair_sync(idA);

            {
                ulonglong2 v0 = xch[(ks * 4 + 0) * 128 + p];
                ulonglong2 v1 = xch[(ks * 4 + 1) * 128 + p];
                ulonglong2 v2 = xch[(ks * 4 + 2) * 128 + p];
                ulonglong2 v3 = xch[(ks * 4 + 3) * 128 + p];
                fadd2(oA[0], v0.x); fadd2(oA[1], v0.y); fadd2(oA[2], v1.x); fadd2(oA[3], v1.y);
                fadd2(oB[0], v2.x); fadd2(oB[1], v2.y); fadd2(oB[2], v3.x); fadd2(oB[3], v3.y);
            }

            float2 vA[4] = {unpack2(oA[0]), unpack2(oA[1]), unpack2(oA[2]), unpack2(oA[3])};
            float2 vB[4] = {unpack2(oB[0]), unpack2(oB[1]), unpack2(oB[2]), unpack2(oB[3])};

            if (ig) {
                float iv[8], gv[8];
#pragma unroll
                for (int q = 0; q < 4; q++) {
                    iv[2 * q] = sigfast(vA[q].x);  iv[2 * q + 1] = sigfast(vA[q].y);
                    gv[2 * q] = tanhfast(vB[q].x); gv[2 * q + 1] = tanhfast(vB[q].y);
                }
                barpair_sync(idB);           // wait for my fo partner's actx
                const float* ab = actx + u * 36 + ks * 16;
                float h[8];
#pragma unroll
                for (int q = 0; q < 8; q++) {
                    float fg = ab[q];
                    float og = ab[8 + q];
                    c8[q] = fg * c8[q] + iv[q] * gv[q];
                    h[q] = og * tanhfast(c8[q]);
                }
                float* d0 = hs + u * ES + 8 * ks;
                *reinterpret_cast<float4*>(d0)     = make_float4(h[0], h[1], h[2], h[3]);
                *reinterpret_cast<float4*>(d0 + 4) = make_float4(h[4], h[5], h[6], h[7]);
            } else {
                float* ab = actx + u * 36 + ks * 16;
                *reinterpret_cast<float4*>(ab)      = make_float4(sigfast(vA[0].x), sigfast(vA[0].y), sigfast(vA[1].x), sigfast(vA[1].y));
                *reinterpret_cast<float4*>(ab + 4)  = make_float4(sigfast(vA[2].x), sigfast(vA[2].y), sigfast(vA[3].x), sigfast(vA[3].y));
                *reinterpret_cast<float4*>(ab + 8)  = make_float4(sigfast(vB[0].x), sigfast(vB[0].y), sigfast(vB[1].x), sigfast(vB[1].y));
                *reinterpret_cast<float4*>(ab + 12) = make_float4(sigfast(vB[2].x), sigfast(vB[2].y), sigfast(vB[3].x), sigfast(vB[3].y));
                barpair_arrive(idB);         // producer does not block
            }
            __syncthreads();
        }
    }

    // ================= Linear head =================
    if (tid < OUTD * EE) {
        int e = tid & (EE - 1);
        int o = tid >> 4;
        float s = blin_s[o];
#pragma unroll
        for (int k = 0; k < HID; k++)
            s += wlin[o * HID + k] * hs[k * ES + e];
        out[(size_t)(e0 + e) * OUTD + o] = s;
    }
}

extern "C" void kernel_launch(void* const* d_in, const int* in_sizes, int n_in,
                              void* d_out, int out_size)
{
    const float* x    = (const float*)d_in[0];
    const float* Wih0 = (const float*)d_in[1];
    const float* Whh0 = (const float*)d_in[2];
    const float* bih0 = (const float*)d_in[3];
    const float* bhh0 = (const float*)d_in[4];
    const float* Wih1 = (const float*)d_in[5];
    const float* Whh1 = (const float*)d_in[6];
    const float* bih1 = (const float*)d_in[7];
    const float* bhh1 = (const float*)d_in[8];
    const float* Wlin = (const float*)d_in[9];
    const float* blin = (const float*)d_in[10];
    float* out = (float*)d_out;

    int B = in_sizes[0] / (TT * IND);   // 16384
    int grid = B / EE;                  // 1024

    cudaFuncSetAttribute(rnn_fused_kernel,
                         cudaFuncAttributeMaxDynamicSharedMemorySize, SMEM_BYTES);
    rnn_fused_kernel<<<grid, NT, SMEM_BYTES>>>(
        x, Wih0, Whh0, bih0, bhh0, Wih1, Whh1, bih1, bhh1, Wlin, blin, out);
}